// round 10
// baseline (speedup 1.0000x reference)
#include <cuda_runtime.h>
#include <cuda_fp16.h>
#include <cstdint>

// Problem constants
#define BB   2
#define TT   8192
#define DD   512
#define HH   8
#define WW   256
#define DH   64
#define NC   32

// ---------------------------------------------------------------------------
// Static device scratch (single rn-fp16 representations; err ~2^-12)
// ---------------------------------------------------------------------------
__device__ __half g_xh[(size_t)BB * TT * DD];
__device__ __half g_Wh[4 * DD * DD];                // q,k,v,o stacked
__device__ __half g_Qh[(size_t)BB * HH * TT * DH];
__device__ __half g_Kh[(size_t)BB * HH * TT * DH];
__device__ __half g_Vh[(size_t)BB * HH * TT * DH];
__device__ __half g_Oh[(size_t)BB * TT * DD];

// ---------------------------------------------------------------------------
// Helpers (base sm_103 features only: mma.sync / ldmatrix / cp.async)
// ---------------------------------------------------------------------------
__device__ __forceinline__ uint32_t smem_to_u32(const void* p) {
    uint32_t a;
    asm("{ .reg .u64 t; cvta.to.shared.u64 t, %1; cvt.u32.u64 %0, t; }"
        : "=r"(a) : "l"(p));
    return a;
}

#define SWZ128(b) ((b) ^ (((b) >> 3) & 0x70))

__device__ __forceinline__ void cp16(uint32_t dst, const void* src) {
    asm volatile("cp.async.cg.shared.global [%0], [%1], 16;" :: "r"(dst), "l"(src) : "memory");
}
#define CP_COMMIT() asm volatile("cp.async.commit_group;" ::: "memory")
#define CP_WAIT(N)  asm volatile("cp.async.wait_group %0;" :: "n"(N) : "memory")

#define LDSM_X4(R, ADDR) \
    asm volatile("ldmatrix.sync.aligned.m8n8.x4.shared.b16 {%0,%1,%2,%3}, [%4];" \
        : "=r"((R)[0]), "=r"((R)[1]), "=r"((R)[2]), "=r"((R)[3]) : "r"(ADDR))

#define LDSM_X4T(R, ADDR) \
    asm volatile("ldmatrix.sync.aligned.m8n8.x4.trans.shared.b16 {%0,%1,%2,%3}, [%4];" \
        : "=r"((R)[0]), "=r"((R)[1]), "=r"((R)[2]), "=r"((R)[3]) : "r"(ADDR))

__device__ __forceinline__ void mma_f16(float c[4], const uint32_t a[4],
                                        uint32_t b0, uint32_t b1) {
    asm volatile(
        "mma.sync.aligned.m16n8k16.row.col.f32.f16.f16.f32 "
        "{%0,%1,%2,%3}, {%4,%5,%6,%7}, {%8,%9}, {%0,%1,%2,%3};"
        : "+f"(c[0]), "+f"(c[1]), "+f"(c[2]), "+f"(c[3])
        : "r"(a[0]), "r"(a[1]), "r"(a[2]), "r"(a[3]), "r"(b0), "r"(b1));
}

__device__ __forceinline__ uint32_t pack_h2(float a, float b) {
    __half2 h = __floats2half2_rn(a, b);
    return *reinterpret_cast<uint32_t*>(&h);
}

// ---------------------------------------------------------------------------
// Input prep: x and 4 W matrices -> rn fp16
// ---------------------------------------------------------------------------
#define NX4 ((BB * TT * DD) / 4)
#define NW4 ((DD * DD) / 4)

__global__ void __launch_bounds__(256) convert_inputs(
    const float4* __restrict__ x,
    const float4* __restrict__ wq, const float4* __restrict__ wk,
    const float4* __restrict__ wv, const float4* __restrict__ wo)
{
    int i = blockIdx.x * 256 + threadIdx.x;
    float4 a;
    uint32_t* dst;
    if (i < NX4) {
        a = x[i];
        dst = (uint32_t*)g_xh + 2 * i;
    } else {
        int j = i - NX4;
        if (j >= 4 * NW4) return;
        int w = j >> 16;            // NW4 = 65536
        int r = j & (NW4 - 1);
        const float4* ws[4] = { wq, wk, wv, wo };
        a = ws[w][r];
        dst = (uint32_t*)g_Wh + 2 * (w * NW4 + r);
    }
    dst[0] = pack_h2(a.x, a.y);
    dst[1] = pack_h2(a.z, a.w);
}

// ---------------------------------------------------------------------------
// fp16 GEMM on mma.sync: C = A W^T + bias
// Block tile 128(m) x 64(n), K-chunks of 64, double-buffered SW128 smem
// (24KB/stage -> 48KB). 8 warps = 4(m) x 2(n); warp tile 32x32 (32 accum).
// __launch_bounds__(256,3): 3 CTAs/SM = 24 warps -> hides LDSM latency that
// bound R9 (all pipes <50%, regs==128).
// MODE 0: rn-fp16 scatter to [B,H,T,d]; z selects Q/K/V.
// MODE 1: fp32 row-major to d_out.
// ---------------------------------------------------------------------------
template <int MODE>
__global__ void __launch_bounds__(256, 3) mma_gemm(
    const __half* __restrict__ A, const __half* __restrict__ WB,
    const float* __restrict__ bias0, const float* __restrict__ bias1,
    const float* __restrict__ bias2,
    __half* __restrict__ outQ, __half* __restrict__ outK,
    __half* __restrict__ outV, float* __restrict__ outF)
{
    constexpr int STG = 24576;   // A 16K + B 8K
    extern __shared__ char smc[];
    const uint32_t su = smem_to_u32(smc);
    const int tid = threadIdx.x, lane = tid & 31, wid = tid >> 5;
    const int wm = wid & 3, wn = wid >> 2;
    const int bm = blockIdx.y * 128, bn = blockIdx.x * 64, z = blockIdx.z;

    const __half* srcA = A + (size_t)bm * DD;
    const __half* srcB = WB + (size_t)z * DD * DD + (size_t)bn * DD;
    const float* bias = (z == 0) ? bias0 : (z == 1 ? bias1 : bias2);

    auto load_stage = [&](int s, int buf) {
        const uint32_t base = su + buf * STG;
        const int k0 = s * 64;
#pragma unroll
        for (int p = 0; p < 6; p++) {
            int idx = p * 256 + tid;
            if (idx < 1024) {               // A: 128 rows x 8 chunks
                int row = idx >> 3, col = idx & 7;
                cp16(base + SWZ128(row * 128 + col * 16),
                     srcA + (size_t)row * DD + k0 + col * 8);
            } else {                        // B: 64 rows x 8 chunks
                int j = idx - 1024;
                int row = j >> 3, col = j & 7;
                cp16(base + 16384 + SWZ128(row * 128 + col * 16),
                     srcB + (size_t)row * DD + k0 + col * 8);
            }
        }
    };

    float c[2][4][4] = {};

    load_stage(0, 0); CP_COMMIT();

    for (int s = 0; s < 8; s++) {
        CP_WAIT(0);
        __syncthreads();
        if (s < 7) { load_stage(s + 1, (s + 1) & 1); CP_COMMIT(); }
        const uint32_t bA = su + (s & 1) * STG;
        const uint32_t bB = bA + 16384;
#pragma unroll
        for (int q = 0; q < 4; q++) {
            uint32_t ah[2][4];
#pragma unroll
            for (int mt = 0; mt < 2; mt++) {
                const int row = wm * 32 + mt * 16 + (lane & 15);
                const uint32_t off = SWZ128(row * 128 + q * 32 + (lane >> 4) * 16);
                LDSM_X4(ah[mt], bA + off);
            }
#pragma unroll
            for (int nt2 = 0; nt2 < 2; nt2++) {
                const int n = wn * 32 + nt2 * 16 + (lane & 7) + ((lane >> 4) & 1) * 8;
                const uint32_t off = SWZ128(n * 128 + q * 32 + ((lane >> 3) & 1) * 16);
                uint32_t bh[4];
                LDSM_X4(bh, bB + off);
#pragma unroll
                for (int mt = 0; mt < 2; mt++) {
                    mma_f16(c[mt][2 * nt2],     ah[mt], bh[0], bh[1]);
                    mma_f16(c[mt][2 * nt2 + 1], ah[mt], bh[2], bh[3]);
                }
            }
        }
    }

    // Epilogue
    __half* dstH = (z == 0) ? outQ : (z == 1 ? outK : outV);
#pragma unroll
    for (int mt = 0; mt < 2; mt++) {
        const int r0 = bm + wm * 32 + mt * 16 + (lane >> 2);   // rows r0 and r0+8
#pragma unroll
        for (int nt = 0; nt < 4; nt++) {
            const int n = bn + wn * 32 + nt * 8 + (lane & 3) * 2;
            const float b0v = bias[n], b1v = bias[n + 1];
            const float v0 = c[mt][nt][0] + b0v, v1 = c[mt][nt][1] + b1v;
            const float v2 = c[mt][nt][2] + b0v, v3 = c[mt][nt][3] + b1v;
            if (MODE == 0) {
                const int hh = n >> 6, j = n & 63;
                const int bq = r0 >> 13, t = r0 & (TT - 1);
                const size_t off0 = (((size_t)bq * HH + hh) * TT + t) * DH + j;
                const size_t off1 = off0 + 8 * DH;   // row+8 -> t+8
                *(uint32_t*)(dstH + off0) = pack_h2(v0, v1);
                *(uint32_t*)(dstH + off1) = pack_h2(v2, v3);
            } else {
                float2 p0; p0.x = v0; p0.y = v1;
                float2 p1; p1.x = v2; p1.y = v3;
                *(float2*)(outF + (size_t)r0 * DD + n) = p0;
                *(float2*)(outF + (size_t)(r0 + 8) * DD + n) = p1;
            }
        }
    }
}

// ---------------------------------------------------------------------------
// Local attention on mma.sync, fp16 (arithmetic identical to R8: rel_err
// calibrated 6.6e-4).
// One block = 128 queries; 256 threads = 8 warps, warp = 16 query rows.
// Per-16-key interleaving (S -> exp/pack -> PV) caps live registers at
// ~80 -> __launch_bounds__(256,3): 24 warps/SM (was 12-16).
// KV ring: 3 x 16K + 16K Q staging = 64K smem (192K/SM at 3 CTAs).
// ---------------------------------------------------------------------------
__global__ void __launch_bounds__(256, 3) attn_mma()
{
    extern __shared__ char smc[];
    const uint32_t su = smem_to_u32(smc);
    const int tid = threadIdx.x, lane = tid & 31, wid = tid >> 5;  // 8 warps
    const int bid = blockIdx.x;
    const int qb = bid & 63;                 // 64 query-blocks of 128 per (b,h)
    const int h = (bid >> 6) & (HH - 1);
    const int b = bid >> 9;
    const int qstart = qb * 128;
    const int c = qb >> 1;                   // 256-wide chunk index

    const size_t hb = ((size_t)(b * HH + h)) * TT * DH;
    const __half* Qp = g_Qh + hb;
    const __half* Kp = g_Kh + hb;
    const __half* Vp = g_Vh + hb;

    const int k0 = (c == 0) ? 0 : (c - 1) * WW;
    const int k1 = (c == NC - 1) ? TT : (c + 2) * WW;
    const int ntiles = (k1 - k0) >> 6;       // 8 or 12

    const uint32_t BUF0 = su;                // 3 x 16K ring (K 8K + V 8K)
    const uint32_t QSTG = su + 3 * 16384;    // 16K Q staging

    auto load_kv = [&](int i, int buf) {
        const int kt = k0 + i * 64;
        const uint32_t base = BUF0 + buf * 16384;
#pragma unroll
        for (int p = 0; p < 4; p++) {
            int idx = p * 256 + tid;
            int mtx = idx >> 9, row = (idx >> 3) & 63, col = idx & 7;
            cp16(base + mtx * 8192 + SWZ128(row * 128 + col * 16),
                 (mtx ? Vp : Kp) + (size_t)(kt + row) * DH + col * 8);
        }
    };

    // Prologue: Q -> QSTG + KV0 (group 0); KV1 (group 1)
#pragma unroll
    for (int p = 0; p < 4; p++) {
        int idx = p * 256 + tid;
        int row = idx >> 3, col = idx & 7;
        cp16(QSTG + SWZ128(row * 128 + col * 16),
             Qp + (size_t)(qstart + row) * DH + col * 8);
    }
    load_kv(0, 0);
    CP_COMMIT();                 // g0: Q + KV0
    load_kv(1, 1); CP_COMMIT();  // g1: KV1

    float o[8][4] = {};
    float lsum0 = 0.f, lsum1 = 0.f;
    uint32_t qh[4][4];           // [k16 chunk][regs], loop-invariant

    auto compute = [&](uint32_t kb) {
#pragma unroll
        for (int kt2 = 0; kt2 < 4; kt2++) {      // 16 keys at a time
            // S(m16 x n16): 8 MMAs, 4 K-LDSM
            float sfr[2][4] = {};
#pragma unroll
            for (int q = 0; q < 4; q++) {
                const int n = kt2 * 16 + (lane & 7) + ((lane >> 4) & 1) * 8;
                const uint32_t off = SWZ128(n * 128 + q * 32 + ((lane >> 3) & 1) * 16);
                uint32_t kh[4];
                LDSM_X4(kh, kb + off);
                mma_f16(sfr[0], qh[q], kh[0], kh[1]);
                mma_f16(sfr[1], qh[q], kh[2], kh[3]);
            }

            // p = rn_fp16(exp(s/8)); lsum sums the ROUNDED weights
            uint32_t ap[4];
            {
                float e0 = __expf(sfr[0][0] * 0.125f);
                float e1 = __expf(sfr[0][1] * 0.125f);
                float e2 = __expf(sfr[0][2] * 0.125f);
                float e3 = __expf(sfr[0][3] * 0.125f);
                float f0 = __expf(sfr[1][0] * 0.125f);
                float f1 = __expf(sfr[1][1] * 0.125f);
                float f2 = __expf(sfr[1][2] * 0.125f);
                float f3 = __expf(sfr[1][3] * 0.125f);
                __half2 he01 = __floats2half2_rn(e0, e1);
                __half2 he23 = __floats2half2_rn(e2, e3);
                __half2 hf01 = __floats2half2_rn(f0, f1);
                __half2 hf23 = __floats2half2_rn(f2, f3);
                ap[0] = *reinterpret_cast<uint32_t*>(&he01);
                ap[1] = *reinterpret_cast<uint32_t*>(&he23);
                ap[2] = *reinterpret_cast<uint32_t*>(&hf01);
                ap[3] = *reinterpret_cast<uint32_t*>(&hf23);
                lsum0 += __low2float(he01) + __high2float(he01)
                       + __low2float(hf01) + __high2float(hf01);
                lsum1 += __low2float(he23) + __high2float(he23)
                       + __low2float(hf23) + __high2float(hf23);
            }

            // O += P V: 8 MMAs, 4 V-LDSM (16-key contraction step)
#pragma unroll
            for (int nt2 = 0; nt2 < 4; nt2++) {
                const int kr = kt2 * 16 + (lane & 7) + ((lane >> 4) & 1) * 8;
                const uint32_t off = SWZ128(kr * 128 + nt2 * 32 + ((lane >> 3) & 1) * 16);
                uint32_t vh[4];
                LDSM_X4T(vh, kb + 8192 + off);
                mma_f16(o[2 * nt2],     ap, vh[0], vh[2]);
                mma_f16(o[2 * nt2 + 1], ap, vh[1], vh[3]);
            }
        }
    };

    // Iter 0: wait g0 (Q + KV0), extract Q fragments
    CP_WAIT(1);
    __syncthreads();
#pragma unroll
    for (int q = 0; q < 4; q++) {
        const int row = wid * 16 + (lane & 15);
        const uint32_t off = SWZ128(row * 128 + q * 32 + (lane >> 4) * 16);
        LDSM_X4(qh[q], QSTG + off);
    }
    if (2 < ntiles) load_kv(2, 2);
    CP_COMMIT();                          // g2 (possibly empty)
    compute(BUF0);

    for (int i = 1; i < ntiles; i++) {
        CP_WAIT(1);
        __syncthreads();
        if (i + 2 < ntiles) load_kv(i + 2, (i + 2) % 3);
        CP_COMMIT();
        compute(BUF0 + (i % 3) * 16384);
    }

    // normalize + store (rn fp16 to [B,T,D])
    lsum0 += __shfl_xor_sync(0xffffffffu, lsum0, 1);
    lsum0 += __shfl_xor_sync(0xffffffffu, lsum0, 2);
    lsum1 += __shfl_xor_sync(0xffffffffu, lsum1, 1);
    lsum1 += __shfl_xor_sync(0xffffffffu, lsum1, 2);
    const float inv0 = 1.f / lsum0, inv1 = 1.f / lsum1;

    const int r0 = wid * 16 + (lane >> 2);
    const int t0g = qstart + r0;
    const size_t o0 = ((size_t)b * TT + t0g) * DD + h * DH + (lane & 3) * 2;
    const size_t o1 = o0 + (size_t)8 * DD;
#pragma unroll
    for (int nt = 0; nt < 8; nt++) {
        *(uint32_t*)(g_Oh + o0 + nt * 8) = pack_h2(o[nt][0] * inv0, o[nt][1] * inv0);
        *(uint32_t*)(g_Oh + o1 + nt * 8) = pack_h2(o[nt][2] * inv1, o[nt][3] * inv1);
    }
}

// ---------------------------------------------------------------------------
extern "C" void kernel_launch(void* const* d_in, const int* in_sizes, int n_in,
                              void* d_out, int out_size)
{
    const float* x  = (const float*)d_in[0];
    const float* Wq = (const float*)d_in[1];
    const float* bq = (const float*)d_in[2];
    const float* Wk = (const float*)d_in[3];
    const float* bk = (const float*)d_in[4];
    const float* Wv = (const float*)d_in[5];
    const float* bv = (const float*)d_in[6];
    const float* Wo = (const float*)d_in[7];
    const float* bo = (const float*)d_in[8];
    float* out = (float*)d_out;

    __half *xh, *Wh, *Qh, *Kh, *Vh, *Oh;
    cudaGetSymbolAddress((void**)&xh, g_xh);
    cudaGetSymbolAddress((void**)&Wh, g_Wh);
    cudaGetSymbolAddress((void**)&Qh, g_Qh);
    cudaGetSymbolAddress((void**)&Kh, g_Kh);
    cudaGetSymbolAddress((void**)&Vh, g_Vh);
    cudaGetSymbolAddress((void**)&Oh, g_Oh);

    const int SMEM_G = 49152;              // 2 x 24K
    const int SMEM_A = 65536;              // 3 x 16K ring + 16K Q
    cudaFuncSetAttribute(mma_gemm<0>, cudaFuncAttributeMaxDynamicSharedMemorySize, SMEM_G);
    cudaFuncSetAttribute(mma_gemm<1>, cudaFuncAttributeMaxDynamicSharedMemorySize, SMEM_G);
    cudaFuncSetAttribute(attn_mma,    cudaFuncAttributeMaxDynamicSharedMemorySize, SMEM_A);

    // Input conversion (fp32 -> rn fp16)
    const int ntot = NX4 + 4 * NW4;
    convert_inputs<<<(ntot + 255) / 256, 256>>>(
        (const float4*)x, (const float4*)Wq, (const float4*)Wk,
        (const float4*)Wv, (const float4*)Wo);

    // QKV projections (1-MMA), scatter rn-fp16 to [B,H,T,d]
    dim3 gqkv(DD / 64, (BB * TT) / 128, 3);
    mma_gemm<0><<<gqkv, 256, SMEM_G>>>(xh, Wh, bq, bk, bv, Qh, Kh, Vh, nullptr);

    // Local attention (rn-fp16 out in [B,T,D])
    attn_mma<<<BB * HH * (TT / 128), 256, SMEM_A>>>();

    // Output projection (1-MMA) -> fp32 d_out
    dim3 gproj(DD / 64, (BB * TT) / 128, 1);
    mma_gemm<1><<<gproj, 256, SMEM_G>>>(Oh, Wh + (size_t)3 * DD * DD,
                                        bo, bo, bo,
                                        nullptr, nullptr, nullptr, out);
}

// round 11
// speedup vs baseline: 1.0291x; 1.0291x over previous
#include <cuda_runtime.h>
#include <cuda_fp16.h>
#include <cstdint>

// Problem constants
#define BB   2
#define TT   8192
#define DD   512
#define HH   8
#define WW   256
#define DH   64
#define NC   32

// ---------------------------------------------------------------------------
// Static device scratch (single rn-fp16 representations; err ~2^-12)
// ---------------------------------------------------------------------------
__device__ __half g_xh[(size_t)BB * TT * DD];
__device__ __half g_Wh[4 * DD * DD];                // q,k,v,o stacked
__device__ __half g_Qh[(size_t)BB * HH * TT * DH];
__device__ __half g_Kh[(size_t)BB * HH * TT * DH];
__device__ __half g_Vh[(size_t)BB * HH * TT * DH];
__device__ __half g_Oh[(size_t)BB * TT * DD];

// ---------------------------------------------------------------------------
// Helpers (base sm_103 features only: mma.sync / ldmatrix / cp.async)
// ---------------------------------------------------------------------------
__device__ __forceinline__ uint32_t smem_to_u32(const void* p) {
    uint32_t a;
    asm("{ .reg .u64 t; cvta.to.shared.u64 t, %1; cvt.u32.u64 %0, t; }"
        : "=r"(a) : "l"(p));
    return a;
}

#define SWZ128(b) ((b) ^ (((b) >> 3) & 0x70))

__device__ __forceinline__ void cp16(uint32_t dst, const void* src) {
    asm volatile("cp.async.cg.shared.global [%0], [%1], 16;" :: "r"(dst), "l"(src) : "memory");
}
#define CP_COMMIT() asm volatile("cp.async.commit_group;" ::: "memory")
#define CP_WAIT(N)  asm volatile("cp.async.wait_group %0;" :: "n"(N) : "memory")

#define LDSM_X4(R, ADDR) \
    asm volatile("ldmatrix.sync.aligned.m8n8.x4.shared.b16 {%0,%1,%2,%3}, [%4];" \
        : "=r"((R)[0]), "=r"((R)[1]), "=r"((R)[2]), "=r"((R)[3]) : "r"(ADDR))

#define LDSM_X4T(R, ADDR) \
    asm volatile("ldmatrix.sync.aligned.m8n8.x4.trans.shared.b16 {%0,%1,%2,%3}, [%4];" \
        : "=r"((R)[0]), "=r"((R)[1]), "=r"((R)[2]), "=r"((R)[3]) : "r"(ADDR))

__device__ __forceinline__ void mma_f16(float c[4], const uint32_t a[4],
                                        uint32_t b0, uint32_t b1) {
    asm volatile(
        "mma.sync.aligned.m16n8k16.row.col.f32.f16.f16.f32 "
        "{%0,%1,%2,%3}, {%4,%5,%6,%7}, {%8,%9}, {%0,%1,%2,%3};"
        : "+f"(c[0]), "+f"(c[1]), "+f"(c[2]), "+f"(c[3])
        : "r"(a[0]), "r"(a[1]), "r"(a[2]), "r"(a[3]), "r"(b0), "r"(b1));
}

__device__ __forceinline__ uint32_t pack_h2(float a, float b) {
    __half2 h = __floats2half2_rn(a, b);
    return *reinterpret_cast<uint32_t*>(&h);
}

// ---------------------------------------------------------------------------
// Input prep: x and 4 W matrices -> rn fp16
// ---------------------------------------------------------------------------
#define NX4 ((BB * TT * DD) / 4)
#define NW4 ((DD * DD) / 4)

__global__ void __launch_bounds__(256) convert_inputs(
    const float4* __restrict__ x,
    const float4* __restrict__ wq, const float4* __restrict__ wk,
    const float4* __restrict__ wv, const float4* __restrict__ wo)
{
    int i = blockIdx.x * 256 + threadIdx.x;
    float4 a;
    uint32_t* dst;
    if (i < NX4) {
        a = x[i];
        dst = (uint32_t*)g_xh + 2 * i;
    } else {
        int j = i - NX4;
        if (j >= 4 * NW4) return;
        int w = j >> 16;            // NW4 = 65536
        int r = j & (NW4 - 1);
        const float4* ws[4] = { wq, wk, wv, wo };
        a = ws[w][r];
        dst = (uint32_t*)g_Wh + 2 * (w * NW4 + r);
    }
    dst[0] = pack_h2(a.x, a.y);
    dst[1] = pack_h2(a.z, a.w);
}

// ---------------------------------------------------------------------------
// fp16 GEMM on mma.sync: C = A W^T + bias
// Block tile 128(m) x 64(n), K-chunks of 64, double-buffered SW128 smem
// (24KB/stage -> 48KB). 8 warps = 4(m) x 2(n); warp tile 32x32 (32 accum).
// __launch_bounds__(256,2): reg cap 128 (not 84) so ptxas can software-
// pipeline LDSM->MMA fragment loads (R10's (256,3) capped at 84 blocked it).
// MODE 0: rn-fp16 scatter to [B,H,T,d]; z selects Q/K/V.
// MODE 1: fp32 row-major to d_out.
// ---------------------------------------------------------------------------
template <int MODE>
__global__ void __launch_bounds__(256, 2) mma_gemm(
    const __half* __restrict__ A, const __half* __restrict__ WB,
    const float* __restrict__ bias0, const float* __restrict__ bias1,
    const float* __restrict__ bias2,
    __half* __restrict__ outQ, __half* __restrict__ outK,
    __half* __restrict__ outV, float* __restrict__ outF)
{
    constexpr int STG = 24576;   // A 16K + B 8K
    extern __shared__ char smc[];
    const uint32_t su = smem_to_u32(smc);
    const int tid = threadIdx.x, lane = tid & 31, wid = tid >> 5;
    const int wm = wid & 3, wn = wid >> 2;
    const int bm = blockIdx.y * 128, bn = blockIdx.x * 64, z = blockIdx.z;

    const __half* srcA = A + (size_t)bm * DD;
    const __half* srcB = WB + (size_t)z * DD * DD + (size_t)bn * DD;
    const float* bias = (z == 0) ? bias0 : (z == 1 ? bias1 : bias2);

    auto load_stage = [&](int s, int buf) {
        const uint32_t base = su + buf * STG;
        const int k0 = s * 64;
#pragma unroll
        for (int p = 0; p < 6; p++) {
            int idx = p * 256 + tid;
            if (idx < 1024) {               // A: 128 rows x 8 chunks
                int row = idx >> 3, col = idx & 7;
                cp16(base + SWZ128(row * 128 + col * 16),
                     srcA + (size_t)row * DD + k0 + col * 8);
            } else {                        // B: 64 rows x 8 chunks
                int j = idx - 1024;
                int row = j >> 3, col = j & 7;
                cp16(base + 16384 + SWZ128(row * 128 + col * 16),
                     srcB + (size_t)row * DD + k0 + col * 8);
            }
        }
    };

    float c[2][4][4] = {};

    load_stage(0, 0); CP_COMMIT();

    for (int s = 0; s < 8; s++) {
        CP_WAIT(0);
        __syncthreads();
        if (s < 7) { load_stage(s + 1, (s + 1) & 1); CP_COMMIT(); }
        const uint32_t bA = su + (s & 1) * STG;
        const uint32_t bB = bA + 16384;
#pragma unroll
        for (int q = 0; q < 4; q++) {
            uint32_t ah[2][4];
#pragma unroll
            for (int mt = 0; mt < 2; mt++) {
                const int row = wm * 32 + mt * 16 + (lane & 15);
                const uint32_t off = SWZ128(row * 128 + q * 32 + (lane >> 4) * 16);
                LDSM_X4(ah[mt], bA + off);
            }
#pragma unroll
            for (int nt2 = 0; nt2 < 2; nt2++) {
                const int n = wn * 32 + nt2 * 16 + (lane & 7) + ((lane >> 4) & 1) * 8;
                const uint32_t off = SWZ128(n * 128 + q * 32 + ((lane >> 3) & 1) * 16);
                uint32_t bh[4];
                LDSM_X4(bh, bB + off);
#pragma unroll
                for (int mt = 0; mt < 2; mt++) {
                    mma_f16(c[mt][2 * nt2],     ah[mt], bh[0], bh[1]);
                    mma_f16(c[mt][2 * nt2 + 1], ah[mt], bh[2], bh[3]);
                }
            }
        }
    }

    // Epilogue
    __half* dstH = (z == 0) ? outQ : (z == 1 ? outK : outV);
#pragma unroll
    for (int mt = 0; mt < 2; mt++) {
        const int r0 = bm + wm * 32 + mt * 16 + (lane >> 2);   // rows r0 and r0+8
#pragma unroll
        for (int nt = 0; nt < 4; nt++) {
            const int n = bn + wn * 32 + nt * 8 + (lane & 3) * 2;
            const float b0v = bias[n], b1v = bias[n + 1];
            const float v0 = c[mt][nt][0] + b0v, v1 = c[mt][nt][1] + b1v;
            const float v2 = c[mt][nt][2] + b0v, v3 = c[mt][nt][3] + b1v;
            if (MODE == 0) {
                const int hh = n >> 6, j = n & 63;
                const int bq = r0 >> 13, t = r0 & (TT - 1);
                const size_t off0 = (((size_t)bq * HH + hh) * TT + t) * DH + j;
                const size_t off1 = off0 + 8 * DH;   // row+8 -> t+8
                *(uint32_t*)(dstH + off0) = pack_h2(v0, v1);
                *(uint32_t*)(dstH + off1) = pack_h2(v2, v3);
            } else {
                float2 p0; p0.x = v0; p0.y = v1;
                float2 p1; p1.x = v2; p1.y = v3;
                *(float2*)(outF + (size_t)r0 * DD + n) = p0;
                *(float2*)(outF + (size_t)(r0 + 8) * DD + n) = p1;
            }
        }
    }
}

// ---------------------------------------------------------------------------
// Local attention on mma.sync, fp16 (arithmetic identical to R8: rel_err
// calibrated 6.6e-4).
// One block = 128 queries; 128 threads = 4 warps, warp = 32 query rows
// (2 m16 frags). Each K/V LDSM now feeds 4 MMAs in a run (was 2):
// MMA/LDSM = 4.0 for the whole mainloop -- the one knob that separated the
// 68%-tensor R4 shape from every 45% shape.
// Q fragments hoisted (32 regs); per-16-key interleave caps live sfr/ap.
// __launch_bounds__(128,3): reg cap 170 -> no spill at ~140 usage.
// Smem: 2 x 16K KV ring (double buffer) + 16K Q staging = 48K -> 3 CTAs/SM.
// ---------------------------------------------------------------------------
__global__ void __launch_bounds__(128, 3) attn_mma()
{
    extern __shared__ char smc[];
    const uint32_t su = smem_to_u32(smc);
    const int tid = threadIdx.x, lane = tid & 31, wid = tid >> 5;  // 4 warps
    const int bid = blockIdx.x;
    const int qb = bid & 63;                 // 64 query-blocks of 128 per (b,h)
    const int h = (bid >> 6) & (HH - 1);
    const int b = bid >> 9;
    const int qstart = qb * 128;
    const int c = qb >> 1;                   // 256-wide chunk index

    const size_t hb = ((size_t)(b * HH + h)) * TT * DH;
    const __half* Qp = g_Qh + hb;
    const __half* Kp = g_Kh + hb;
    const __half* Vp = g_Vh + hb;

    const int k0 = (c == 0) ? 0 : (c - 1) * WW;
    const int k1 = (c == NC - 1) ? TT : (c + 2) * WW;
    const int ntiles = (k1 - k0) >> 6;       // 8 or 12

    const uint32_t BUF0 = su;                // 2 x 16K ring (K 8K + V 8K)
    const uint32_t QSTG = su + 2 * 16384;    // 16K Q staging (persistent)

    auto load_kv = [&](int i, int buf) {
        const int kt = k0 + i * 64;
        const uint32_t base = BUF0 + buf * 16384;
#pragma unroll
        for (int p = 0; p < 8; p++) {
            int idx = p * 128 + tid;
            int mtx = idx >> 9, row = (idx >> 3) & 63, col = idx & 7;
            cp16(base + mtx * 8192 + SWZ128(row * 128 + col * 16),
                 (mtx ? Vp : Kp) + (size_t)(kt + row) * DH + col * 8);
        }
    };

    // Prologue: Q -> QSTG + KV0, one group
#pragma unroll
    for (int p = 0; p < 8; p++) {
        int idx = p * 128 + tid;
        int row = idx >> 3, col = idx & 7;
        cp16(QSTG + SWZ128(row * 128 + col * 16),
             Qp + (size_t)(qstart + row) * DH + col * 8);
    }
    load_kv(0, 0);
    CP_COMMIT();                 // g0: Q + KV0

    float o[2][8][4] = {};
    float lsum[2][2] = {};
    uint32_t qh[2][4][4];        // [m-frag][k16 chunk][regs], loop-invariant

    auto compute = [&](uint32_t kb) {
#pragma unroll
        for (int kt2 = 0; kt2 < 4; kt2++) {      // 16 keys at a time
            // S(m32 x n16): 4 K-LDSM, 16 MMAs (runs of 4 per LDSM)
            float sfr[2][2][4] = {};
#pragma unroll
            for (int q = 0; q < 4; q++) {
                const int n = kt2 * 16 + (lane & 7) + ((lane >> 4) & 1) * 8;
                const uint32_t off = SWZ128(n * 128 + q * 32 + ((lane >> 3) & 1) * 16);
                uint32_t kh[4];
                LDSM_X4(kh, kb + off);
#pragma unroll
                for (int mf = 0; mf < 2; mf++) {
                    mma_f16(sfr[mf][0], qh[mf][q], kh[0], kh[1]);
                    mma_f16(sfr[mf][1], qh[mf][q], kh[2], kh[3]);
                }
            }

            // p = rn_fp16(exp(s/8)); lsum sums the ROUNDED weights
            uint32_t ap[2][4];
#pragma unroll
            for (int mf = 0; mf < 2; mf++) {
                float e0 = __expf(sfr[mf][0][0] * 0.125f);
                float e1 = __expf(sfr[mf][0][1] * 0.125f);
                float e2 = __expf(sfr[mf][0][2] * 0.125f);
                float e3 = __expf(sfr[mf][0][3] * 0.125f);
                float f0 = __expf(sfr[mf][1][0] * 0.125f);
                float f1 = __expf(sfr[mf][1][1] * 0.125f);
                float f2 = __expf(sfr[mf][1][2] * 0.125f);
                float f3 = __expf(sfr[mf][1][3] * 0.125f);
                __half2 he01 = __floats2half2_rn(e0, e1);
                __half2 he23 = __floats2half2_rn(e2, e3);
                __half2 hf01 = __floats2half2_rn(f0, f1);
                __half2 hf23 = __floats2half2_rn(f2, f3);
                ap[mf][0] = *reinterpret_cast<uint32_t*>(&he01);
                ap[mf][1] = *reinterpret_cast<uint32_t*>(&he23);
                ap[mf][2] = *reinterpret_cast<uint32_t*>(&hf01);
                ap[mf][3] = *reinterpret_cast<uint32_t*>(&hf23);
                lsum[mf][0] += __low2float(he01) + __high2float(he01)
                             + __low2float(hf01) + __high2float(hf01);
                lsum[mf][1] += __low2float(he23) + __high2float(he23)
                             + __low2float(hf23) + __high2float(hf23);
            }

            // O += P V: 4 V-LDSM, 16 MMAs (runs of 4 per LDSM)
#pragma unroll
            for (int nt2 = 0; nt2 < 4; nt2++) {
                const int kr = kt2 * 16 + (lane & 7) + ((lane >> 4) & 1) * 8;
                const uint32_t off = SWZ128(kr * 128 + nt2 * 32 + ((lane >> 3) & 1) * 16);
                uint32_t vh[4];
                LDSM_X4T(vh, kb + 8192 + off);
#pragma unroll
                for (int mf = 0; mf < 2; mf++) {
                    mma_f16(o[mf][2 * nt2],     ap[mf], vh[0], vh[2]);
                    mma_f16(o[mf][2 * nt2 + 1], ap[mf], vh[1], vh[3]);
                }
            }
        }
    };

    for (int i = 0; i < ntiles; i++) {
        CP_WAIT(0);                 // wait for buf(i) (issued last iteration)
        __syncthreads();            // also: all warps done with buf(i+1)'s slot
        if (i == 0) {
            // Q staging is ready (part of g0): extract loop-invariant frags
#pragma unroll
            for (int mf = 0; mf < 2; mf++)
#pragma unroll
                for (int q = 0; q < 4; q++) {
                    const int row = wid * 32 + mf * 16 + (lane & 15);
                    const uint32_t off = SWZ128(row * 128 + q * 32 + (lane >> 4) * 16);
                    LDSM_X4(qh[mf][q], QSTG + off);
                }
        }
        if (i + 1 < ntiles) { load_kv(i + 1, (i + 1) & 1); CP_COMMIT(); }
        compute(BUF0 + (i & 1) * 16384);
    }

    // normalize + store (rn fp16 to [B,T,D])
#pragma unroll
    for (int mf = 0; mf < 2; mf++) {
        lsum[mf][0] += __shfl_xor_sync(0xffffffffu, lsum[mf][0], 1);
        lsum[mf][0] += __shfl_xor_sync(0xffffffffu, lsum[mf][0], 2);
        lsum[mf][1] += __shfl_xor_sync(0xffffffffu, lsum[mf][1], 1);
        lsum[mf][1] += __shfl_xor_sync(0xffffffffu, lsum[mf][1], 2);
        const float inv0 = 1.f / lsum[mf][0], inv1 = 1.f / lsum[mf][1];

        const int r0 = wid * 32 + mf * 16 + (lane >> 2);
        const int t0g = qstart + r0;
        const size_t o0 = ((size_t)b * TT + t0g) * DD + h * DH + (lane & 3) * 2;
        const size_t o1 = o0 + (size_t)8 * DD;
#pragma unroll
        for (int nt = 0; nt < 8; nt++) {
            *(uint32_t*)(g_Oh + o0 + nt * 8) = pack_h2(o[mf][nt][0] * inv0, o[mf][nt][1] * inv0);
            *(uint32_t*)(g_Oh + o1 + nt * 8) = pack_h2(o[mf][nt][2] * inv1, o[mf][nt][3] * inv1);
        }
    }
}

// ---------------------------------------------------------------------------
extern "C" void kernel_launch(void* const* d_in, const int* in_sizes, int n_in,
                              void* d_out, int out_size)
{
    const float* x  = (const float*)d_in[0];
    const float* Wq = (const float*)d_in[1];
    const float* bq = (const float*)d_in[2];
    const float* Wk = (const float*)d_in[3];
    const float* bk = (const float*)d_in[4];
    const float* Wv = (const float*)d_in[5];
    const float* bv = (const float*)d_in[6];
    const float* Wo = (const float*)d_in[7];
    const float* bo = (const float*)d_in[8];
    float* out = (float*)d_out;

    __half *xh, *Wh, *Qh, *Kh, *Vh, *Oh;
    cudaGetSymbolAddress((void**)&xh, g_xh);
    cudaGetSymbolAddress((void**)&Wh, g_Wh);
    cudaGetSymbolAddress((void**)&Qh, g_Qh);
    cudaGetSymbolAddress((void**)&Kh, g_Kh);
    cudaGetSymbolAddress((void**)&Vh, g_Vh);
    cudaGetSymbolAddress((void**)&Oh, g_Oh);

    const int SMEM_G = 49152;              // 2 x 24K
    const int SMEM_A = 49152;              // 2 x 16K ring + 16K Q
    cudaFuncSetAttribute(mma_gemm<0>, cudaFuncAttributeMaxDynamicSharedMemorySize, SMEM_G);
    cudaFuncSetAttribute(mma_gemm<1>, cudaFuncAttributeMaxDynamicSharedMemorySize, SMEM_G);
    cudaFuncSetAttribute(attn_mma,    cudaFuncAttributeMaxDynamicSharedMemorySize, SMEM_A);

    // Input conversion (fp32 -> rn fp16)
    const int ntot = NX4 + 4 * NW4;
    convert_inputs<<<(ntot + 255) / 256, 256>>>(
        (const float4*)x, (const float4*)Wq, (const float4*)Wk,
        (const float4*)Wv, (const float4*)Wo);

    // QKV projections (1-MMA), scatter rn-fp16 to [B,H,T,d]
    dim3 gqkv(DD / 64, (BB * TT) / 128, 3);
    mma_gemm<0><<<gqkv, 256, SMEM_G>>>(xh, Wh, bq, bk, bv, Qh, Kh, Vh, nullptr);

    // Local attention (rn-fp16 out in [B,T,D])
    attn_mma<<<BB * HH * (TT / 128), 128, SMEM_A>>>();

    // Output projection (1-MMA) -> fp32 d_out
    dim3 gproj(DD / 64, (BB * TT) / 128, 1);
    mma_gemm<1><<<gproj, 256, SMEM_G>>>(Oh, Wh + (size_t)3 * DD * DD,
                                        bo, bo, bo,
                                        nullptr, nullptr, nullptr, out);
}